// round 1
// baseline (speedup 1.0000x reference)
#include <cuda_runtime.h>

#define B_   2
#define T_   1024
#define NE_  1024
#define CD_  1024
#define NH_  16
#define OD_  4096   // NE + 3*CD

// Scratch (static device globals: allowed; no runtime allocation)
__device__ float g_tok[B_ * T_ * OD_];   // 32 MB
__device__ float g_con[B_ * T_ * OD_];   // 32 MB
__device__ float g_yt [B_ * T_ * NE_];   // 8 MB
__device__ float g_yc [B_ * T_ * CD_];   // 8 MB

// ---------------------------------------------------------------------------
// SGEMM: C[M,N] = A[M,K] @ W[N,K]^T + bias[N]
// 128x128 block tile, BK=16, 256 threads, 8x8 micro-tile per thread.
// All dims divisible by tile sizes for this problem (M=2048, N in {4096,1024}, K=1024).
// ---------------------------------------------------------------------------
__global__ __launch_bounds__(256) void sgemm_bias(
    const float* __restrict__ A, const float* __restrict__ W,
    const float* __restrict__ bias, float* __restrict__ C,
    int M, int N, int K)
{
    const int BK = 16;
    __shared__ float As[16][128];   // [k][m]
    __shared__ float Bs[16][128];   // [k][n]

    int tid = threadIdx.x;
    int tx = tid & 15, ty = tid >> 4;
    int m0 = blockIdx.y * 128, n0 = blockIdx.x * 128;

    float acc[8][8];
#pragma unroll
    for (int i = 0; i < 8; i++)
#pragma unroll
        for (int j = 0; j < 8; j++) acc[i][j] = 0.f;

    for (int k0 = 0; k0 < K; k0 += BK) {
#pragma unroll
        for (int it = 0; it < 2; it++) {
            int f = tid + it * 256;          // 0..511
            int row = f >> 2;                // 0..127
            int kq = (f & 3) << 2;           // 0,4,8,12
            float4 v = *(const float4*)(A + (size_t)(m0 + row) * K + k0 + kq);
            As[kq + 0][row] = v.x; As[kq + 1][row] = v.y;
            As[kq + 2][row] = v.z; As[kq + 3][row] = v.w;
            float4 w = *(const float4*)(W + (size_t)(n0 + row) * K + k0 + kq);
            Bs[kq + 0][row] = w.x; Bs[kq + 1][row] = w.y;
            Bs[kq + 2][row] = w.z; Bs[kq + 3][row] = w.w;
        }
        __syncthreads();
#pragma unroll
        for (int k = 0; k < BK; k++) {
            float a[8], b[8];
            *(float4*)&a[0] = *(float4*)&As[k][ty * 8];
            *(float4*)&a[4] = *(float4*)&As[k][ty * 8 + 4];
            *(float4*)&b[0] = *(float4*)&Bs[k][tx * 8];
            *(float4*)&b[4] = *(float4*)&Bs[k][tx * 8 + 4];
#pragma unroll
            for (int i = 0; i < 8; i++)
#pragma unroll
                for (int j = 0; j < 8; j++)
                    acc[i][j] += a[i] * b[j];
        }
        __syncthreads();
    }

#pragma unroll
    for (int i = 0; i < 8; i++) {
        int m = m0 + ty * 8 + i;
#pragma unroll
        for (int j = 0; j < 8; j += 4) {
            int n = n0 + tx * 8 + j;
            float4 v;
            v.x = acc[i][j + 0] + bias[n + 0];
            v.y = acc[i][j + 1] + bias[n + 1];
            v.z = acc[i][j + 2] + bias[n + 2];
            v.w = acc[i][j + 3] + bias[n + 3];
            *(float4*)(C + (size_t)m * N + n) = v;
        }
    }
}

// ---------------------------------------------------------------------------
// Flash attention over two key segments with stream-specific masks.
// mode 0 (token queries):  segA = token keys (causal), segB = concept keys
//                          (allowed iff j*ntc <= qi)
// mode 1 (concept queries): segA = concept keys (causal), segB = token keys
//                          (allowed iff j < ntc*(qi+1))
// 64 queries x 64 head-dim per block, 64-key tiles, 256 threads (16x16, 4x4).
// ---------------------------------------------------------------------------
__global__ __launch_bounds__(256) void flash_attn(
    const float* __restrict__ Qsrc,
    const float* __restrict__ kA, const float* __restrict__ vA,
    const float* __restrict__ kB, const float* __restrict__ vB,
    float* __restrict__ Out,
    const int* __restrict__ ntc_ptr, int mode)
{
    __shared__ float Qs[64][64];   // [d][i]  (Q transposed)
    __shared__ float KP[64][64];   // phase 1: K transposed [d][j]; phase 2: P [i][j]
    __shared__ float Vs[64][64];   // [j][c]

    int tid = threadIdx.x;
    int tx = tid & 15, ty = tid >> 4;
    int q0 = blockIdx.x * 64;
    int h  = blockIdx.y;
    int b  = blockIdx.z;
    int ntc = *ntc_ptr;

    // Load Q tile (transposed)
    const float* qb = Qsrc + (size_t)b * T_ * 1024 + h * 64;
#pragma unroll
    for (int it = 0; it < 4; it++) {
        int f = tid + it * 256;      // 0..1023 float4s
        int row = f >> 4;            // 0..63
        int dq = (f & 15) << 2;      // 0..60
        float4 v = *(const float4*)(qb + (size_t)(q0 + row) * 1024 + dq);
        Qs[dq + 0][row] = v.x; Qs[dq + 1][row] = v.y;
        Qs[dq + 2][row] = v.z; Qs[dq + 3][row] = v.w;
    }

    float mrow[4], lrow[4], o[4][4];
#pragma unroll
    for (int i = 0; i < 4; i++) {
        mrow[i] = -1e30f; lrow[i] = 0.f;
#pragma unroll
        for (int j = 0; j < 4; j++) o[i][j] = 0.f;
    }

    const float scale = 0.125f;   // 1/sqrt(64)
    int qe = q0 + 63;

    for (int seg = 0; seg < 2; seg++) {
        const float* kp = (seg == 0) ? kA : kB;
        const float* vp = (seg == 0) ? vA : vB;
        int lim;
        if (seg == 0)           lim = qe;
        else if (mode == 0)     lim = qe / ntc;
        else                    lim = ntc * (qe + 1) - 1;
        if (lim > T_ - 1) lim = T_ - 1;
        int ntiles = (lim >> 6) + 1;

        const float* kbb = kp + (size_t)b * T_ * OD_ + h * 64;
        const float* vbb = vp + (size_t)b * T_ * OD_ + h * 64;

        for (int t = 0; t < ntiles; t++) {
            int ks = t << 6;
            __syncthreads();   // protect KP/Vs from previous iteration readers
            // Load K (transposed) + V tiles
#pragma unroll
            for (int it = 0; it < 4; it++) {
                int f = tid + it * 256;
                int row = f >> 4;
                int dq = (f & 15) << 2;
                float4 v = *(const float4*)(kbb + (size_t)(ks + row) * OD_ + dq);
                KP[dq + 0][row] = v.x; KP[dq + 1][row] = v.y;
                KP[dq + 2][row] = v.z; KP[dq + 3][row] = v.w;
                float4 w = *(const float4*)(vbb + (size_t)(ks + row) * OD_ + dq);
                *(float4*)&Vs[row][dq] = w;
            }
            __syncthreads();

            // S = Q K^T (4x4 per thread)
            float s[4][4];
#pragma unroll
            for (int i = 0; i < 4; i++)
#pragma unroll
                for (int j = 0; j < 4; j++) s[i][j] = 0.f;
#pragma unroll 8
            for (int d = 0; d < 64; d++) {
                float a[4], bb[4];
                *(float4*)a  = *(float4*)&Qs[d][ty * 4];
                *(float4*)bb = *(float4*)&KP[d][tx * 4];
#pragma unroll
                for (int i = 0; i < 4; i++)
#pragma unroll
                    for (int j = 0; j < 4; j++)
                        s[i][j] += a[i] * bb[j];
            }
            __syncthreads();   // done reading K; KP becomes P buffer

            // mask + online softmax; write P into KP
#pragma unroll
            for (int i = 0; i < 4; i++) {
                int qi = q0 + ty * 4 + i;
                float mloc = -1e30f;
#pragma unroll
                for (int j = 0; j < 4; j++) {
                    int kj = ks + tx * 4 + j;
                    bool okm;
                    if (seg == 0)        okm = (kj <= qi);
                    else if (mode == 0)  okm = (kj * ntc <= qi);
                    else                 okm = (kj < ntc * (qi + 1));
                    float sv = okm ? s[i][j] * scale : -1e30f;
                    s[i][j] = sv;
                    mloc = fmaxf(mloc, sv);
                }
#pragma unroll
                for (int off = 8; off >= 1; off >>= 1)
                    mloc = fmaxf(mloc, __shfl_xor_sync(0xffffffffu, mloc, off));
                float mnew = fmaxf(mrow[i], mloc);
                float alpha = __expf(mrow[i] - mnew);
                float p[4];
                float lsum = 0.f;
#pragma unroll
                for (int j = 0; j < 4; j++) {
                    p[j] = __expf(s[i][j] - mnew);
                    lsum += p[j];
                }
#pragma unroll
                for (int off = 8; off >= 1; off >>= 1)
                    lsum += __shfl_xor_sync(0xffffffffu, lsum, off);
                lrow[i] = lrow[i] * alpha + lsum;
                mrow[i] = mnew;
#pragma unroll
                for (int j = 0; j < 4; j++) o[i][j] *= alpha;
                *(float4*)&KP[ty * 4 + i][tx * 4] = *(float4*)p;
            }
            __syncthreads();

            // O += P V
#pragma unroll
            for (int j4 = 0; j4 < 64; j4 += 4) {
                float pr[4][4], vv[4][4];
#pragma unroll
                for (int i = 0; i < 4; i++)
                    *(float4*)pr[i] = *(float4*)&KP[ty * 4 + i][j4];
#pragma unroll
                for (int u = 0; u < 4; u++)
                    *(float4*)vv[u] = *(float4*)&Vs[j4 + u][tx * 4];
#pragma unroll
                for (int i = 0; i < 4; i++)
#pragma unroll
                    for (int u = 0; u < 4; u++)
#pragma unroll
                        for (int c = 0; c < 4; c++)
                            o[i][c] += pr[i][u] * vv[u][c];
            }
        }
    }

    // Epilogue: normalize, write (B,T,1024) row-major
#pragma unroll
    for (int i = 0; i < 4; i++) {
        float inv = 1.f / lrow[i];
        int row = q0 + ty * 4 + i;
        float4 v;
        v.x = o[i][0] * inv; v.y = o[i][1] * inv;
        v.z = o[i][2] * inv; v.w = o[i][3] * inv;
        *(float4*)(Out + (size_t)(b * T_ + row) * 1024 + h * 64 + tx * 4) = v;
    }
}

// ---------------------------------------------------------------------------
extern "C" void kernel_launch(void* const* d_in, const int* in_sizes, int n_in,
                              void* d_out, int out_size)
{
    const float* xt  = (const float*)d_in[0];
    const float* xc  = (const float*)d_in[1];
    const float* Wt  = (const float*)d_in[2];
    const float* bt  = (const float*)d_in[3];
    const float* Wc  = (const float*)d_in[4];
    const float* bc  = (const float*)d_in[5];
    const float* Wtp = (const float*)d_in[6];
    const float* btp = (const float*)d_in[7];
    const float* Wcp = (const float*)d_in[8];
    const float* bcp = (const float*)d_in[9];
    const int*   ntc = (const int*)d_in[10];
    float* out = (float*)d_out;

    float *tok, *con, *yt, *yc;
    cudaGetSymbolAddress((void**)&tok, g_tok);
    cudaGetSymbolAddress((void**)&con, g_con);
    cudaGetSymbolAddress((void**)&yt,  g_yt);
    cudaGetSymbolAddress((void**)&yc,  g_yc);

    const int M = B_ * T_;   // 2048

    // 1) Input projections: tok = xt@Wt^T+bt, con = xc@Wc^T+bc
    dim3 g1(OD_ / 128, M / 128);   // (32, 16)
    sgemm_bias<<<g1, 256>>>(xt, Wt, bt, tok, M, OD_, NE_);
    sgemm_bias<<<g1, 256>>>(xc, Wc, bc, con, M, OD_, CD_);

    // 2) Attention
    dim3 ga(T_ / 64, NH_, B_);     // (16, 16, 2)
    // token queries: keys = [tok cols 0..NE ; con cols 0..NE],
    //                vals = [tok cols NE+CD.. ; con cols NE+CD..]
    flash_attn<<<ga, 256>>>(xt,
                            tok + 0,            tok + (NE_ + CD_),
                            con + 0,            con + (NE_ + CD_),
                            yt, ntc, 0);
    // concept queries: keys = [con cols NE.. ; tok cols NE..],
    //                  vals = [con cols NE+2CD.. ; tok cols NE+2CD..]
    flash_attn<<<ga, 256>>>(xc,
                            con + NE_,          con + (NE_ + 2 * CD_),
                            tok + NE_,          tok + (NE_ + 2 * CD_),
                            yc, ntc, 1);

    // 3) Output projections into d_out: [y_t ; y_c]
    dim3 g2(NE_ / 128, M / 128);   // (8, 16)
    sgemm_bias<<<g2, 256>>>(yt, Wtp, btp, out,                          M, NE_, NE_);
    sgemm_bias<<<g2, 256>>>(yc, Wcp, bcp, out + (size_t)M * NE_,        M, CD_, CD_);
}

// round 2
// speedup vs baseline: 1.5231x; 1.5231x over previous
#include <cuda_runtime.h>
#include <cstdint>

#define B_   2
#define T_   1024
#define NE_  1024
#define CD_  1024
#define NH_  16
#define OD_  4096   // NE + 3*CD

// Scratch (static device globals: allowed; no runtime allocation)
__device__ float g_tok[B_ * T_ * OD_];   // 32 MB
__device__ float g_con[B_ * T_ * OD_];   // 32 MB
__device__ float g_yt [B_ * T_ * NE_];   // 8 MB
__device__ float g_yc [B_ * T_ * CD_];   // 8 MB

// ---------------------------------------------------------------------------
// TF32 tensor-core GEMM: C[M,N] = A[M,K] @ W[N,K]^T + bias[N]
// Block tile 128x128, BK=16, 256 threads (8 warps, 2(M) x 4(N)).
// Warp tile 64x32 -> 4x4 grid of m16n8k8 mma.sync tiles.
// Smem rows padded to 20 words -> conflict-free fragment loads.
// ---------------------------------------------------------------------------
__device__ __forceinline__ uint32_t f2tf32(float x) {
    uint32_t r;
    asm("cvt.rna.tf32.f32 %0, %1;" : "=r"(r) : "f"(x));
    return r;
}

__device__ __forceinline__ void mma_tf32(float d[4], const uint32_t a[4], const uint32_t b[2]) {
    asm volatile(
        "mma.sync.aligned.m16n8k8.row.col.f32.tf32.tf32.f32 "
        "{%0,%1,%2,%3}, {%4,%5,%6,%7}, {%8,%9}, {%10,%11,%12,%13};\n"
        : "=f"(d[0]), "=f"(d[1]), "=f"(d[2]), "=f"(d[3])
        : "r"(a[0]), "r"(a[1]), "r"(a[2]), "r"(a[3]),
          "r"(b[0]), "r"(b[1]),
          "f"(d[0]), "f"(d[1]), "f"(d[2]), "f"(d[3]));
}

__global__ __launch_bounds__(256) void gemm_tf32(
    const float* __restrict__ A, const float* __restrict__ W,
    const float* __restrict__ bias, float* __restrict__ C,
    int M, int N, int K)
{
    __shared__ uint32_t As[128][20];   // [m][k], padded
    __shared__ uint32_t Ws[128][20];   // [n][k], padded

    int tid  = threadIdx.x;
    int warp = tid >> 5;
    int lane = tid & 31;
    int g  = lane >> 2;    // 0..7
    int tg = lane & 3;     // 0..3

    int warp_m = warp & 1;       // 2 warps in M
    int warp_n = warp >> 1;      // 4 warps in N
    int mbw = warp_m * 64;
    int nbw = warp_n * 32;

    int m0 = blockIdx.y * 128;
    int n0 = blockIdx.x * 128;

    float acc[4][4][4];
#pragma unroll
    for (int mt = 0; mt < 4; mt++)
#pragma unroll
        for (int nt = 0; nt < 4; nt++)
#pragma unroll
            for (int r = 0; r < 4; r++) acc[mt][nt][r] = 0.f;

    for (int k0 = 0; k0 < K; k0 += 16) {
        // Stage tiles (convert to tf32 on the way in).
        // 128*16 = 2048 floats per tile = 512 float4; 256 threads -> 2 each.
#pragma unroll
        for (int it = 0; it < 2; it++) {
            int idx = tid + it * 256;        // 0..511
            int row = idx >> 2;              // 0..127
            int kq  = (idx & 3) << 2;        // 0,4,8,12
            float4 va = *(const float4*)(A + (size_t)(m0 + row) * K + k0 + kq);
            uint4 ua;
            ua.x = f2tf32(va.x); ua.y = f2tf32(va.y);
            ua.z = f2tf32(va.z); ua.w = f2tf32(va.w);
            *(uint4*)&As[row][kq] = ua;
            float4 vw = *(const float4*)(W + (size_t)(n0 + row) * K + k0 + kq);
            uint4 uw;
            uw.x = f2tf32(vw.x); uw.y = f2tf32(vw.y);
            uw.z = f2tf32(vw.z); uw.w = f2tf32(vw.w);
            *(uint4*)&Ws[row][kq] = uw;
        }
        __syncthreads();

#pragma unroll
        for (int ks = 0; ks < 16; ks += 8) {
            uint32_t af[4][4];
#pragma unroll
            for (int mt = 0; mt < 4; mt++) {
                int r0 = mbw + mt * 16 + g;
                af[mt][0] = As[r0][ks + tg];
                af[mt][1] = As[r0 + 8][ks + tg];
                af[mt][2] = As[r0][ks + tg + 4];
                af[mt][3] = As[r0 + 8][ks + tg + 4];
            }
            uint32_t bf[4][2];
#pragma unroll
            for (int nt = 0; nt < 4; nt++) {
                int c0 = nbw + nt * 8 + g;
                bf[nt][0] = Ws[c0][ks + tg];
                bf[nt][1] = Ws[c0][ks + tg + 4];
            }
#pragma unroll
            for (int mt = 0; mt < 4; mt++)
#pragma unroll
                for (int nt = 0; nt < 4; nt++)
                    mma_tf32(acc[mt][nt], af[mt], bf[nt]);
        }
        __syncthreads();
    }

    // Epilogue: bias + store. c0/c1 at (row, 2tg),(row, 2tg+1); c2/c3 at row+8.
#pragma unroll
    for (int nt = 0; nt < 4; nt++) {
        int col = n0 + nbw + nt * 8 + tg * 2;
        float2 bb = *(const float2*)(bias + col);
#pragma unroll
        for (int mt = 0; mt < 4; mt++) {
            int row = m0 + mbw + mt * 16 + g;
            float2 v0, v1;
            v0.x = acc[mt][nt][0] + bb.x;
            v0.y = acc[mt][nt][1] + bb.y;
            v1.x = acc[mt][nt][2] + bb.x;
            v1.y = acc[mt][nt][3] + bb.y;
            *(float2*)(C + (size_t)row * N + col)       = v0;
            *(float2*)(C + (size_t)(row + 8) * N + col) = v1;
        }
    }
}

// ---------------------------------------------------------------------------
// Flash attention over two key segments with stream-specific masks.
// (unchanged from round 1 — single-change discipline; mma port next round)
// ---------------------------------------------------------------------------
__global__ __launch_bounds__(256) void flash_attn(
    const float* __restrict__ Qsrc,
    const float* __restrict__ kA, const float* __restrict__ vA,
    const float* __restrict__ kB, const float* __restrict__ vB,
    float* __restrict__ Out,
    const int* __restrict__ ntc_ptr, int mode)
{
    __shared__ float Qs[64][64];   // [d][i]  (Q transposed)
    __shared__ float KP[64][64];   // phase 1: K transposed [d][j]; phase 2: P [i][j]
    __shared__ float Vs[64][64];   // [j][c]

    int tid = threadIdx.x;
    int tx = tid & 15, ty = tid >> 4;
    int q0 = blockIdx.x * 64;
    int h  = blockIdx.y;
    int b  = blockIdx.z;
    int ntc = *ntc_ptr;

    const float* qb = Qsrc + (size_t)b * T_ * 1024 + h * 64;
#pragma unroll
    for (int it = 0; it < 4; it++) {
        int f = tid + it * 256;
        int row = f >> 4;
        int dq = (f & 15) << 2;
        float4 v = *(const float4*)(qb + (size_t)(q0 + row) * 1024 + dq);
        Qs[dq + 0][row] = v.x; Qs[dq + 1][row] = v.y;
        Qs[dq + 2][row] = v.z; Qs[dq + 3][row] = v.w;
    }

    float mrow[4], lrow[4], o[4][4];
#pragma unroll
    for (int i = 0; i < 4; i++) {
        mrow[i] = -1e30f; lrow[i] = 0.f;
#pragma unroll
        for (int j = 0; j < 4; j++) o[i][j] = 0.f;
    }

    const float scale = 0.125f;
    int qe = q0 + 63;

    for (int seg = 0; seg < 2; seg++) {
        const float* kp = (seg == 0) ? kA : kB;
        const float* vp = (seg == 0) ? vA : vB;
        int lim;
        if (seg == 0)           lim = qe;
        else if (mode == 0)     lim = qe / ntc;
        else                    lim = ntc * (qe + 1) - 1;
        if (lim > T_ - 1) lim = T_ - 1;
        int ntiles = (lim >> 6) + 1;

        const float* kbb = kp + (size_t)b * T_ * OD_ + h * 64;
        const float* vbb = vp + (size_t)b * T_ * OD_ + h * 64;

        for (int t = 0; t < ntiles; t++) {
            int ks = t << 6;
            __syncthreads();
#pragma unroll
            for (int it = 0; it < 4; it++) {
                int f = tid + it * 256;
                int row = f >> 4;
                int dq = (f & 15) << 2;
                float4 v = *(const float4*)(kbb + (size_t)(ks + row) * OD_ + dq);
                KP[dq + 0][row] = v.x; KP[dq + 1][row] = v.y;
                KP[dq + 2][row] = v.z; KP[dq + 3][row] = v.w;
                float4 w = *(const float4*)(vbb + (size_t)(ks + row) * OD_ + dq);
                *(float4*)&Vs[row][dq] = w;
            }
            __syncthreads();

            float s[4][4];
#pragma unroll
            for (int i = 0; i < 4; i++)
#pragma unroll
                for (int j = 0; j < 4; j++) s[i][j] = 0.f;
#pragma unroll 8
            for (int d = 0; d < 64; d++) {
                float a[4], bb[4];
                *(float4*)a  = *(float4*)&Qs[d][ty * 4];
                *(float4*)bb = *(float4*)&KP[d][tx * 4];
#pragma unroll
                for (int i = 0; i < 4; i++)
#pragma unroll
                    for (int j = 0; j < 4; j++)
                        s[i][j] += a[i] * bb[j];
            }
            __syncthreads();

#pragma unroll
            for (int i = 0; i < 4; i++) {
                int qi = q0 + ty * 4 + i;
                float mloc = -1e30f;
#pragma unroll
                for (int j = 0; j < 4; j++) {
                    int kj = ks + tx * 4 + j;
                    bool okm;
                    if (seg == 0)        okm = (kj <= qi);
                    else if (mode == 0)  okm = (kj * ntc <= qi);
                    else                 okm = (kj < ntc * (qi + 1));
                    float sv = okm ? s[i][j] * scale : -1e30f;
                    s[i][j] = sv;
                    mloc = fmaxf(mloc, sv);
                }
#pragma unroll
                for (int off = 8; off >= 1; off >>= 1)
                    mloc = fmaxf(mloc, __shfl_xor_sync(0xffffffffu, mloc, off));
                float mnew = fmaxf(mrow[i], mloc);
                float alpha = __expf(mrow[i] - mnew);
                float p[4];
                float lsum = 0.f;
#pragma unroll
                for (int j = 0; j < 4; j++) {
                    p[j] = __expf(s[i][j] - mnew);
                    lsum += p[j];
                }
#pragma unroll
                for (int off = 8; off >= 1; off >>= 1)
                    lsum += __shfl_xor_sync(0xffffffffu, lsum, off);
                lrow[i] = lrow[i] * alpha + lsum;
                mrow[i] = mnew;
#pragma unroll
                for (int j = 0; j < 4; j++) o[i][j] *= alpha;
                *(float4*)&KP[ty * 4 + i][tx * 4] = *(float4*)p;
            }
            __syncthreads();

#pragma unroll
            for (int j4 = 0; j4 < 64; j4 += 4) {
                float pr[4][4], vv[4][4];
#pragma unroll
                for (int i = 0; i < 4; i++)
                    *(float4*)pr[i] = *(float4*)&KP[ty * 4 + i][j4];
#pragma unroll
                for (int u = 0; u < 4; u++)
                    *(float4*)vv[u] = *(float4*)&Vs[j4 + u][tx * 4];
#pragma unroll
                for (int i = 0; i < 4; i++)
#pragma unroll
                    for (int u = 0; u < 4; u++)
#pragma unroll
                        for (int c = 0; c < 4; c++)
                            o[i][c] += pr[i][u] * vv[u][c];
            }
        }
    }

#pragma unroll
    for (int i = 0; i < 4; i++) {
        float inv = 1.f / lrow[i];
        int row = q0 + ty * 4 + i;
        float4 v;
        v.x = o[i][0] * inv; v.y = o[i][1] * inv;
        v.z = o[i][2] * inv; v.w = o[i][3] * inv;
        *(float4*)(Out + (size_t)(b * T_ + row) * 1024 + h * 64 + tx * 4) = v;
    }
}

// ---------------------------------------------------------------------------
extern "C" void kernel_launch(void* const* d_in, const int* in_sizes, int n_in,
                              void* d_out, int out_size)
{
    const float* xt  = (const float*)d_in[0];
    const float* xc  = (const float*)d_in[1];
    const float* Wt  = (const float*)d_in[2];
    const float* bt  = (const float*)d_in[3];
    const float* Wc  = (const float*)d_in[4];
    const float* bc  = (const float*)d_in[5];
    const float* Wtp = (const float*)d_in[6];
    const float* btp = (const float*)d_in[7];
    const float* Wcp = (const float*)d_in[8];
    const float* bcp = (const float*)d_in[9];
    const int*   ntc = (const int*)d_in[10];
    float* out = (float*)d_out;

    float *tok, *con, *yt, *yc;
    cudaGetSymbolAddress((void**)&tok, g_tok);
    cudaGetSymbolAddress((void**)&con, g_con);
    cudaGetSymbolAddress((void**)&yt,  g_yt);
    cudaGetSymbolAddress((void**)&yc,  g_yc);

    const int M = B_ * T_;   // 2048

    // 1) Input projections (tf32 tensor cores)
    dim3 g1(OD_ / 128, M / 128);   // (32, 16)
    gemm_tf32<<<g1, 256>>>(xt, Wt, bt, tok, M, OD_, NE_);
    gemm_tf32<<<g1, 256>>>(xc, Wc, bc, con, M, OD_, CD_);

    // 2) Attention
    dim3 ga(T_ / 64, NH_, B_);     // (16, 16, 2)
    flash_attn<<<ga, 256>>>(xt,
                            tok + 0,            tok + (NE_ + CD_),
                            con + 0,            con + (NE_ + CD_),
                            yt, ntc, 0);
    flash_attn<<<ga, 256>>>(xc,
                            con + NE_,          con + (NE_ + 2 * CD_),
                            tok + NE_,          tok + (NE_ + 2 * CD_),
                            yc, ntc, 1);

    // 3) Output projections into d_out: [y_t ; y_c]
    dim3 g2(NE_ / 128, M / 128);   // (8, 16)
    gemm_tf32<<<g2, 256>>>(yt, Wtp, btp, out,                   M, NE_, NE_);
    gemm_tf32<<<g2, 256>>>(yc, Wcp, bcp, out + (size_t)M * NE_, M, CD_, CD_);
}

// round 3
// speedup vs baseline: 2.7482x; 1.8043x over previous
#include <cuda_runtime.h>
#include <cstdint>

#define B_   2
#define T_   1024
#define NE_  1024
#define CD_  1024
#define NH_  16
#define OD_  4096   // NE + 3*CD

// Scratch (static device globals: allowed; no runtime allocation)
__device__ float g_tok[B_ * T_ * OD_];   // 32 MB
__device__ float g_con[B_ * T_ * OD_];   // 32 MB
__device__ float g_yt [B_ * T_ * NE_];   // 8 MB
__device__ float g_yc [B_ * T_ * CD_];   // 8 MB

__device__ __forceinline__ uint32_t f2tf32(float x) {
    uint32_t r;
    asm("cvt.rna.tf32.f32 %0, %1;" : "=r"(r) : "f"(x));
    return r;
}

__device__ __forceinline__ void mma_tf32(float d[4], const uint32_t a[4], const uint32_t b[2]) {
    asm volatile(
        "mma.sync.aligned.m16n8k8.row.col.f32.tf32.tf32.f32 "
        "{%0,%1,%2,%3}, {%4,%5,%6,%7}, {%8,%9}, {%10,%11,%12,%13};\n"
        : "=f"(d[0]), "=f"(d[1]), "=f"(d[2]), "=f"(d[3])
        : "r"(a[0]), "r"(a[1]), "r"(a[2]), "r"(a[3]),
          "r"(b[0]), "r"(b[1]),
          "f"(d[0]), "f"(d[1]), "f"(d[2]), "f"(d[3]));
}

// ---------------------------------------------------------------------------
// TF32 tensor-core GEMM: C[M,N] = A[M,K] @ W[N,K]^T + bias[N]
// (unchanged from round 2)
// ---------------------------------------------------------------------------
__global__ __launch_bounds__(256) void gemm_tf32(
    const float* __restrict__ A, const float* __restrict__ W,
    const float* __restrict__ bias, float* __restrict__ C,
    int M, int N, int K)
{
    __shared__ uint32_t As[128][20];
    __shared__ uint32_t Ws[128][20];

    int tid  = threadIdx.x;
    int warp = tid >> 5;
    int lane = tid & 31;
    int g  = lane >> 2;
    int tg = lane & 3;

    int warp_m = warp & 1;
    int warp_n = warp >> 1;
    int mbw = warp_m * 64;
    int nbw = warp_n * 32;

    int m0 = blockIdx.y * 128;
    int n0 = blockIdx.x * 128;

    float acc[4][4][4];
#pragma unroll
    for (int mt = 0; mt < 4; mt++)
#pragma unroll
        for (int nt = 0; nt < 4; nt++)
#pragma unroll
            for (int r = 0; r < 4; r++) acc[mt][nt][r] = 0.f;

    for (int k0 = 0; k0 < K; k0 += 16) {
#pragma unroll
        for (int it = 0; it < 2; it++) {
            int idx = tid + it * 256;
            int row = idx >> 2;
            int kq  = (idx & 3) << 2;
            float4 va = *(const float4*)(A + (size_t)(m0 + row) * K + k0 + kq);
            uint4 ua;
            ua.x = f2tf32(va.x); ua.y = f2tf32(va.y);
            ua.z = f2tf32(va.z); ua.w = f2tf32(va.w);
            *(uint4*)&As[row][kq] = ua;
            float4 vw = *(const float4*)(W + (size_t)(n0 + row) * K + k0 + kq);
            uint4 uw;
            uw.x = f2tf32(vw.x); uw.y = f2tf32(vw.y);
            uw.z = f2tf32(vw.z); uw.w = f2tf32(vw.w);
            *(uint4*)&Ws[row][kq] = uw;
        }
        __syncthreads();

#pragma unroll
        for (int ks = 0; ks < 16; ks += 8) {
            uint32_t af[4][4];
#pragma unroll
            for (int mt = 0; mt < 4; mt++) {
                int r0 = mbw + mt * 16 + g;
                af[mt][0] = As[r0][ks + tg];
                af[mt][1] = As[r0 + 8][ks + tg];
                af[mt][2] = As[r0][ks + tg + 4];
                af[mt][3] = As[r0 + 8][ks + tg + 4];
            }
            uint32_t bf[4][2];
#pragma unroll
            for (int nt = 0; nt < 4; nt++) {
                int c0 = nbw + nt * 8 + g;
                bf[nt][0] = Ws[c0][ks + tg];
                bf[nt][1] = Ws[c0][ks + tg + 4];
            }
#pragma unroll
            for (int mt = 0; mt < 4; mt++)
#pragma unroll
                for (int nt = 0; nt < 4; nt++)
                    mma_tf32(acc[mt][nt], af[mt], bf[nt]);
        }
        __syncthreads();
    }

#pragma unroll
    for (int nt = 0; nt < 4; nt++) {
        int col = n0 + nbw + nt * 8 + tg * 2;
        float2 bb = *(const float2*)(bias + col);
#pragma unroll
        for (int mt = 0; mt < 4; mt++) {
            int row = m0 + mbw + mt * 16 + g;
            float2 v0, v1;
            v0.x = acc[mt][nt][0] + bb.x;
            v0.y = acc[mt][nt][1] + bb.y;
            v1.x = acc[mt][nt][2] + bb.x;
            v1.y = acc[mt][nt][3] + bb.y;
            *(float2*)(C + (size_t)row * N + col)       = v0;
            *(float2*)(C + (size_t)(row + 8) * N + col) = v1;
        }
    }
}

// ---------------------------------------------------------------------------
// TF32 mma flash attention.
// Block: 64 queries x one head. 4 warps, warp w owns query rows 16w..16w+15.
// Key tiles of 64. Q held in A-fragments (pre-scaled by 1/8). K in KPs
// (stride 68: B-frag banks 4g+tg, conflict-free), V in Vs (stride 72:
// B-frag banks 8tg+g, conflict-free). P reuses the K buffer; P's A-fragment
// reads are warp-local so only __syncwarp is needed after the P write.
// ---------------------------------------------------------------------------
__global__ __launch_bounds__(128) void flash_attn_mma(
    const float* __restrict__ Qsrc,
    const float* __restrict__ kA, const float* __restrict__ vA,
    const float* __restrict__ kB, const float* __restrict__ vB,
    float* __restrict__ Out,
    const int* __restrict__ ntc_ptr, int mode)
{
    __shared__ uint32_t KPs[64][68];   // K tile, then P tile
    __shared__ uint32_t Vs[64][72];    // V tile [key][d]

    int tid  = threadIdx.x;
    int warp = tid >> 5;
    int lane = tid & 31;
    int g  = lane >> 2;    // 0..7
    int tg = lane & 3;     // 0..3
    int rowbase = warp * 16;

    int q0 = blockIdx.x * 64;
    int h  = blockIdx.y;
    int b  = blockIdx.z;
    int ntc = *ntc_ptr;

    // ---- Stage Q (pre-scaled by 1/8) through KPs, then load A-fragments ----
    const float* qb = Qsrc + (size_t)b * T_ * 1024 + h * 64;
#pragma unroll
    for (int it = 0; it < 8; it++) {
        int idx = tid + it * 128;          // 0..1023 float4s
        int row = idx >> 4;                // 0..63
        int dq  = (idx & 15) << 2;         // 0..60
        float4 v = *(const float4*)(qb + (size_t)(q0 + row) * 1024 + dq);
        uint4 u;
        u.x = f2tf32(v.x * 0.125f); u.y = f2tf32(v.y * 0.125f);
        u.z = f2tf32(v.z * 0.125f); u.w = f2tf32(v.w * 0.125f);
        *(uint4*)&KPs[row][dq] = u;
    }
    __syncthreads();

    uint32_t qf[8][4];
#pragma unroll
    for (int st = 0; st < 8; st++) {
        int r0 = rowbase + g;
        int c  = st * 8 + tg;
        qf[st][0] = KPs[r0][c];
        qf[st][1] = KPs[r0 + 8][c];
        qf[st][2] = KPs[r0][c + 4];
        qf[st][3] = KPs[r0 + 8][c + 4];
    }

    float m0r = -1e30f, m1r = -1e30f, l0 = 0.f, l1 = 0.f;
    float o[8][4];
#pragma unroll
    for (int nt = 0; nt < 8; nt++)
#pragma unroll
        for (int r = 0; r < 4; r++) o[nt][r] = 0.f;

    int qi0 = q0 + rowbase + g;
    int qi1 = qi0 + 8;
    int qe  = q0 + 63;

    for (int seg = 0; seg < 2; seg++) {
        const float* kp = (seg == 0) ? kA : kB;
        const float* vp = (seg == 0) ? vA : vB;
        int lim;
        if (seg == 0)           lim = qe;
        else if (mode == 0)     lim = qe / ntc;
        else                    lim = ntc * (qe + 1) - 1;
        if (lim > T_ - 1) lim = T_ - 1;
        int ntiles = (lim >> 6) + 1;

        const float* kbb = kp + (size_t)b * T_ * OD_ + h * 64;
        const float* vbb = vp + (size_t)b * T_ * OD_ + h * 64;

        for (int t = 0; t < ntiles; t++) {
            int ks = t << 6;
            __syncthreads();   // prior PV readers of KPs/Vs done
            // ---- Load K, V tiles ----
#pragma unroll
            for (int it = 0; it < 8; it++) {
                int idx = tid + it * 128;
                int row = idx >> 4;
                int dq  = (idx & 15) << 2;
                float4 v = *(const float4*)(kbb + (size_t)(ks + row) * OD_ + dq);
                uint4 u;
                u.x = f2tf32(v.x); u.y = f2tf32(v.y);
                u.z = f2tf32(v.z); u.w = f2tf32(v.w);
                *(uint4*)&KPs[row][dq] = u;
                float4 w = *(const float4*)(vbb + (size_t)(ks + row) * OD_ + dq);
                uint4 uw;
                uw.x = f2tf32(w.x); uw.y = f2tf32(w.y);
                uw.z = f2tf32(w.z); uw.w = f2tf32(w.w);
                *(uint4*)&Vs[row][dq] = uw;
            }
            __syncthreads();

            // ---- S = Q K^T ----
            float s[8][4];
#pragma unroll
            for (int nt = 0; nt < 8; nt++)
#pragma unroll
                for (int r = 0; r < 4; r++) s[nt][r] = 0.f;
#pragma unroll
            for (int st = 0; st < 8; st++) {
#pragma unroll
                for (int nt = 0; nt < 8; nt++) {
                    uint32_t bf[2];
                    bf[0] = KPs[nt * 8 + g][st * 8 + tg];
                    bf[1] = KPs[nt * 8 + g][st * 8 + tg + 4];
                    mma_tf32(s[nt], qf[st], bf);
                }
            }
            __syncthreads();   // all warps done reading K before P overwrite

            // ---- Mask + online softmax ----
            float mx0 = -1e30f, mx1 = -1e30f;
#pragma unroll
            for (int nt = 0; nt < 8; nt++) {
                int kj0 = ks + nt * 8 + 2 * tg;
                int kj1 = kj0 + 1;
                bool a00, a01, a10, a11;
                if (seg == 0) {
                    a00 = kj0 <= qi0; a01 = kj1 <= qi0;
                    a10 = kj0 <= qi1; a11 = kj1 <= qi1;
                } else if (mode == 0) {
                    a00 = kj0 * ntc <= qi0; a01 = kj1 * ntc <= qi0;
                    a10 = kj0 * ntc <= qi1; a11 = kj1 * ntc <= qi1;
                } else {
                    a00 = kj0 < ntc * (qi0 + 1); a01 = kj1 < ntc * (qi0 + 1);
                    a10 = kj0 < ntc * (qi1 + 1); a11 = kj1 < ntc * (qi1 + 1);
                }
                s[nt][0] = a00 ? s[nt][0] : -1e30f;
                s[nt][1] = a01 ? s[nt][1] : -1e30f;
                s[nt][2] = a10 ? s[nt][2] : -1e30f;
                s[nt][3] = a11 ? s[nt][3] : -1e30f;
                mx0 = fmaxf(mx0, fmaxf(s[nt][0], s[nt][1]));
                mx1 = fmaxf(mx1, fmaxf(s[nt][2], s[nt][3]));
            }
            mx0 = fmaxf(mx0, __shfl_xor_sync(0xffffffffu, mx0, 1));
            mx0 = fmaxf(mx0, __shfl_xor_sync(0xffffffffu, mx0, 2));
            mx1 = fmaxf(mx1, __shfl_xor_sync(0xffffffffu, mx1, 1));
            mx1 = fmaxf(mx1, __shfl_xor_sync(0xffffffffu, mx1, 2));

            float mn0 = fmaxf(m0r, mx0);
            float mn1 = fmaxf(m1r, mx1);
            float al0 = __expf(m0r - mn0);
            float al1 = __expf(m1r - mn1);
            float sum0 = 0.f, sum1 = 0.f;
            int r0 = rowbase + g;
#pragma unroll
            for (int nt = 0; nt < 8; nt++) {
                float p00 = __expf(s[nt][0] - mn0);
                float p01 = __expf(s[nt][1] - mn0);
                float p10 = __expf(s[nt][2] - mn1);
                float p11 = __expf(s[nt][3] - mn1);
                sum0 += p00 + p01;
                sum1 += p10 + p11;
                int c = nt * 8 + 2 * tg;
                uint2 u0, u1;
                u0.x = f2tf32(p00); u0.y = f2tf32(p01);
                u1.x = f2tf32(p10); u1.y = f2tf32(p11);
                *(uint2*)&KPs[r0][c]     = u0;
                *(uint2*)&KPs[r0 + 8][c] = u1;
            }
            sum0 += __shfl_xor_sync(0xffffffffu, sum0, 1);
            sum0 += __shfl_xor_sync(0xffffffffu, sum0, 2);
            sum1 += __shfl_xor_sync(0xffffffffu, sum1, 1);
            sum1 += __shfl_xor_sync(0xffffffffu, sum1, 2);
            l0 = l0 * al0 + sum0;
            l1 = l1 * al1 + sum1;
            m0r = mn0;
            m1r = mn1;
#pragma unroll
            for (int nt = 0; nt < 8; nt++) {
                o[nt][0] *= al0; o[nt][1] *= al0;
                o[nt][2] *= al1; o[nt][3] *= al1;
            }
            __syncwarp();   // P rows are warp-local (warp w wrote rows 16w..16w+15)

            // ---- O += P V ----
#pragma unroll
            for (int st = 0; st < 8; st++) {
                uint32_t af[4];
                int c = st * 8 + tg;
                af[0] = KPs[rowbase + g][c];
                af[1] = KPs[rowbase + g + 8][c];
                af[2] = KPs[rowbase + g][c + 4];
                af[3] = KPs[rowbase + g + 8][c + 4];
#pragma unroll
                for (int nt = 0; nt < 8; nt++) {
                    uint32_t bf[2];
                    bf[0] = Vs[st * 8 + tg][nt * 8 + g];
                    bf[1] = Vs[st * 8 + tg + 4][nt * 8 + g];
                    mma_tf32(o[nt], af, bf);
                }
            }
        }
    }

    // ---- Epilogue: normalize, store ----
    float inv0 = 1.f / l0;
    float inv1 = 1.f / l1;
    int row0 = q0 + rowbase + g;
    float* ob = Out + (size_t)b * T_ * 1024 + h * 64;
#pragma unroll
    for (int nt = 0; nt < 8; nt++) {
        int col = nt * 8 + 2 * tg;
        float2 v0, v1;
        v0.x = o[nt][0] * inv0; v0.y = o[nt][1] * inv0;
        v1.x = o[nt][2] * inv1; v1.y = o[nt][3] * inv1;
        *(float2*)(ob + (size_t)row0 * 1024 + col)       = v0;
        *(float2*)(ob + (size_t)(row0 + 8) * 1024 + col) = v1;
    }
}

// ---------------------------------------------------------------------------
extern "C" void kernel_launch(void* const* d_in, const int* in_sizes, int n_in,
                              void* d_out, int out_size)
{
    const float* xt  = (const float*)d_in[0];
    const float* xc  = (const float*)d_in[1];
    const float* Wt  = (const float*)d_in[2];
    const float* bt  = (const float*)d_in[3];
    const float* Wc  = (const float*)d_in[4];
    const float* bc  = (const float*)d_in[5];
    const float* Wtp = (const float*)d_in[6];
    const float* btp = (const float*)d_in[7];
    const float* Wcp = (const float*)d_in[8];
    const float* bcp = (const float*)d_in[9];
    const int*   ntc = (const int*)d_in[10];
    float* out = (float*)d_out;

    float *tok, *con, *yt, *yc;
    cudaGetSymbolAddress((void**)&tok, g_tok);
    cudaGetSymbolAddress((void**)&con, g_con);
    cudaGetSymbolAddress((void**)&yt,  g_yt);
    cudaGetSymbolAddress((void**)&yc,  g_yc);

    const int M = B_ * T_;   // 2048

    // 1) Input projections (tf32 tensor cores)
    dim3 g1(OD_ / 128, M / 128);
    gemm_tf32<<<g1, 256>>>(xt, Wt, bt, tok, M, OD_, NE_);
    gemm_tf32<<<g1, 256>>>(xc, Wc, bc, con, M, OD_, CD_);

    // 2) Attention (tf32 mma)
    dim3 ga(T_ / 64, NH_, B_);
    flash_attn_mma<<<ga, 128>>>(xt,
                                tok + 0,   tok + (NE_ + CD_),
                                con + 0,   con + (NE_ + CD_),
                                yt, ntc, 0);
    flash_attn_mma<<<ga, 128>>>(xc,
                                con + NE_, con + (NE_ + 2 * CD_),
                                tok + NE_, tok + (NE_ + 2 * CD_),
                                yc, ntc, 1);

    // 3) Output projections into d_out: [y_t ; y_c]
    dim3 g2(NE_ / 128, M / 128);
    gemm_tf32<<<g2, 256>>>(yt, Wtp, btp, out,                   M, NE_, NE_);
    gemm_tf32<<<g2, 256>>>(yc, Wcp, bcp, out + (size_t)M * NE_, M, CD_, CD_);
}

// round 4
// speedup vs baseline: 3.1020x; 1.1287x over previous
#include <cuda_runtime.h>
#include <cstdint>

#define B_   2
#define T_   1024
#define NE_  1024
#define CD_  1024
#define NH_  16
#define OD_  4096   // NE + 3*CD

// Scratch (static device globals: allowed; no runtime allocation)
__device__ float g_tok[B_ * T_ * OD_];   // 32 MB
__device__ float g_con[B_ * T_ * OD_];   // 32 MB
__device__ float g_yt [B_ * T_ * NE_];   // 8 MB
__device__ float g_yc [B_ * T_ * CD_];   // 8 MB

__device__ __forceinline__ uint32_t f2tf32(float x) {
    uint32_t r;
    asm("cvt.rna.tf32.f32 %0, %1;" : "=r"(r) : "f"(x));
    return r;
}

__device__ __forceinline__ void mma_tf32(float d[4], const uint32_t a[4], const uint32_t b[2]) {
    asm volatile(
        "mma.sync.aligned.m16n8k8.row.col.f32.tf32.tf32.f32 "
        "{%0,%1,%2,%3}, {%4,%5,%6,%7}, {%8,%9}, {%10,%11,%12,%13};\n"
        : "=f"(d[0]), "=f"(d[1]), "=f"(d[2]), "=f"(d[3])
        : "r"(a[0]), "r"(a[1]), "r"(a[2]), "r"(a[3]),
          "r"(b[0]), "r"(b[1]),
          "f"(d[0]), "f"(d[1]), "f"(d[2]), "f"(d[3]));
}

// ---------------------------------------------------------------------------
// TF32 tensor-core GEMM: C[M,N] = A[M,K] @ W[N,K]^T + bias[N]
// 128x128 tile, BK=16, 256 threads. Double-buffered smem + register
// prefetch: LDGs for tile k+1 issue before the mma block for tile k;
// one __syncthreads per ktile.
// ---------------------------------------------------------------------------
__global__ __launch_bounds__(256) void gemm_tf32(
    const float* __restrict__ A, const float* __restrict__ W,
    const float* __restrict__ bias, float* __restrict__ C,
    int M, int N, int K)
{
    __shared__ uint32_t As[2][128][20];
    __shared__ uint32_t Ws[2][128][20];

    int tid  = threadIdx.x;
    int warp = tid >> 5;
    int lane = tid & 31;
    int g  = lane >> 2;
    int tg = lane & 3;

    int warp_m = warp & 1;
    int warp_n = warp >> 1;
    int mbw = warp_m * 64;
    int nbw = warp_n * 32;

    int m0 = blockIdx.y * 128;
    int n0 = blockIdx.x * 128;

    // Per-thread load coordinates (2 float4 each from A and W per ktile)
    int lrow0 = (tid * 2)     >> 2 >> 1;        // placeholder (recomputed below)
    (void)lrow0;
    int idx0 = tid;            // it = 0
    int idx1 = tid + 256;      // it = 1
    int row0 = idx0 >> 2, kq0 = (idx0 & 3) << 2;
    int row1 = idx1 >> 2, kq1 = (idx1 & 3) << 2;

    const float* Aip0 = A + (size_t)(m0 + row0) * K + kq0;
    const float* Aip1 = A + (size_t)(m0 + row1) * K + kq1;
    const float* Wip0 = W + (size_t)(n0 + row0) * K + kq0;
    const float* Wip1 = W + (size_t)(n0 + row1) * K + kq1;

    float acc[4][4][4];
#pragma unroll
    for (int mt = 0; mt < 4; mt++)
#pragma unroll
        for (int nt = 0; nt < 4; nt++)
#pragma unroll
            for (int r = 0; r < 4; r++) acc[mt][nt][r] = 0.f;

    // Prologue: load + convert + store tile 0 into buffer 0
    {
        float4 va0 = *(const float4*)(Aip0);
        float4 va1 = *(const float4*)(Aip1);
        float4 vw0 = *(const float4*)(Wip0);
        float4 vw1 = *(const float4*)(Wip1);
        uint4 u;
        u.x = f2tf32(va0.x); u.y = f2tf32(va0.y); u.z = f2tf32(va0.z); u.w = f2tf32(va0.w);
        *(uint4*)&As[0][row0][kq0] = u;
        u.x = f2tf32(va1.x); u.y = f2tf32(va1.y); u.z = f2tf32(va1.z); u.w = f2tf32(va1.w);
        *(uint4*)&As[0][row1][kq1] = u;
        u.x = f2tf32(vw0.x); u.y = f2tf32(vw0.y); u.z = f2tf32(vw0.z); u.w = f2tf32(vw0.w);
        *(uint4*)&Ws[0][row0][kq0] = u;
        u.x = f2tf32(vw1.x); u.y = f2tf32(vw1.y); u.z = f2tf32(vw1.z); u.w = f2tf32(vw1.w);
        *(uint4*)&Ws[0][row1][kq1] = u;
    }
    __syncthreads();

    int nkt = K >> 4;
    int buf = 0;
    for (int kt = 0; kt < nkt; kt++) {
        // Prefetch next tile into registers (issues before the mma block)
        float4 va0, va1, vw0, vw1;
        bool more = (kt + 1 < nkt);
        if (more) {
            int off = (kt + 1) << 4;
            va0 = *(const float4*)(Aip0 + off);
            va1 = *(const float4*)(Aip1 + off);
            vw0 = *(const float4*)(Wip0 + off);
            vw1 = *(const float4*)(Wip1 + off);
        }

        // Compute on current buffer
#pragma unroll
        for (int ks = 0; ks < 16; ks += 8) {
            uint32_t af[4][4];
#pragma unroll
            for (int mt = 0; mt < 4; mt++) {
                int r0 = mbw + mt * 16 + g;
                af[mt][0] = As[buf][r0][ks + tg];
                af[mt][1] = As[buf][r0 + 8][ks + tg];
                af[mt][2] = As[buf][r0][ks + tg + 4];
                af[mt][3] = As[buf][r0 + 8][ks + tg + 4];
            }
            uint32_t bf[4][2];
#pragma unroll
            for (int nt = 0; nt < 4; nt++) {
                int c0 = nbw + nt * 8 + g;
                bf[nt][0] = Ws[buf][c0][ks + tg];
                bf[nt][1] = Ws[buf][c0][ks + tg + 4];
            }
#pragma unroll
            for (int mt = 0; mt < 4; mt++)
#pragma unroll
                for (int nt = 0; nt < 4; nt++)
                    mma_tf32(acc[mt][nt], af[mt], bf[nt]);
        }

        // Convert + store prefetched tile into the other buffer
        if (more) {
            int nb = buf ^ 1;
            uint4 u;
            u.x = f2tf32(va0.x); u.y = f2tf32(va0.y); u.z = f2tf32(va0.z); u.w = f2tf32(va0.w);
            *(uint4*)&As[nb][row0][kq0] = u;
            u.x = f2tf32(va1.x); u.y = f2tf32(va1.y); u.z = f2tf32(va1.z); u.w = f2tf32(va1.w);
            *(uint4*)&As[nb][row1][kq1] = u;
            u.x = f2tf32(vw0.x); u.y = f2tf32(vw0.y); u.z = f2tf32(vw0.z); u.w = f2tf32(vw0.w);
            *(uint4*)&Ws[nb][row0][kq0] = u;
            u.x = f2tf32(vw1.x); u.y = f2tf32(vw1.y); u.z = f2tf32(vw1.z); u.w = f2tf32(vw1.w);
            *(uint4*)&Ws[nb][row1][kq1] = u;
            __syncthreads();
        }
        buf ^= 1;
    }

    // Epilogue: bias + store
#pragma unroll
    for (int nt = 0; nt < 4; nt++) {
        int col = n0 + nbw + nt * 8 + tg * 2;
        float2 bb = *(const float2*)(bias + col);
#pragma unroll
        for (int mt = 0; mt < 4; mt++) {
            int row = m0 + mbw + mt * 16 + g;
            float2 v0, v1;
            v0.x = acc[mt][nt][0] + bb.x;
            v0.y = acc[mt][nt][1] + bb.y;
            v1.x = acc[mt][nt][2] + bb.x;
            v1.y = acc[mt][nt][3] + bb.y;
            *(float2*)(C + (size_t)row * N + col)       = v0;
            *(float2*)(C + (size_t)(row + 8) * N + col) = v1;
        }
    }
}

// ---------------------------------------------------------------------------
// TF32 mma flash attention — both attention passes in ONE launch.
// blockIdx.z encodes {batch, mode}: mode = z>>1, b = z&1.
// Heavy q-tiles scheduled first (reversed blockIdx.x) to shrink the
// straggler tail from causal work imbalance.
// ---------------------------------------------------------------------------
__global__ __launch_bounds__(128) void flash_attn_mma(
    const float* __restrict__ xt, const float* __restrict__ xc,
    const float* __restrict__ tok, const float* __restrict__ con,
    float* __restrict__ yt, float* __restrict__ yc,
    const int* __restrict__ ntc_ptr)
{
    __shared__ uint32_t KPs[64][68];   // K tile, then P tile
    __shared__ uint32_t Vs[64][72];    // V tile [key][d]

    int tid  = threadIdx.x;
    int warp = tid >> 5;
    int lane = tid & 31;
    int g  = lane >> 2;    // 0..7
    int tg = lane & 3;     // 0..3
    int rowbase = warp * 16;

    int q0 = ((int)gridDim.x - 1 - (int)blockIdx.x) * 64;   // heavy tiles first
    int h  = blockIdx.y;
    int b  = blockIdx.z & 1;
    int mode = blockIdx.z >> 1;
    int ntc = *ntc_ptr;

    const float* Qsrc;
    const float* kA; const float* vA;
    const float* kB; const float* vB;
    float* Out;
    if (mode == 0) {
        Qsrc = xt;
        kA = tok;                    vA = tok + (NE_ + CD_);
        kB = con;                    vB = con + (NE_ + CD_);
        Out = yt;
    } else {
        Qsrc = xc;
        kA = con + NE_;              vA = con + (NE_ + 2 * CD_);
        kB = tok + NE_;              vB = tok + (NE_ + 2 * CD_);
        Out = yc;
    }

    // ---- Stage Q (pre-scaled by 1/8) through KPs, then load A-fragments ----
    const float* qb = Qsrc + (size_t)b * T_ * 1024 + h * 64;
#pragma unroll
    for (int it = 0; it < 8; it++) {
        int idx = tid + it * 128;
        int row = idx >> 4;
        int dq  = (idx & 15) << 2;
        float4 v = *(const float4*)(qb + (size_t)(q0 + row) * 1024 + dq);
        uint4 u;
        u.x = f2tf32(v.x * 0.125f); u.y = f2tf32(v.y * 0.125f);
        u.z = f2tf32(v.z * 0.125f); u.w = f2tf32(v.w * 0.125f);
        *(uint4*)&KPs[row][dq] = u;
    }
    __syncthreads();

    uint32_t qf[8][4];
#pragma unroll
    for (int st = 0; st < 8; st++) {
        int r0 = rowbase + g;
        int c  = st * 8 + tg;
        qf[st][0] = KPs[r0][c];
        qf[st][1] = KPs[r0 + 8][c];
        qf[st][2] = KPs[r0][c + 4];
        qf[st][3] = KPs[r0 + 8][c + 4];
    }

    float m0r = -1e30f, m1r = -1e30f, l0 = 0.f, l1 = 0.f;
    float o[8][4];
#pragma unroll
    for (int nt = 0; nt < 8; nt++)
#pragma unroll
        for (int r = 0; r < 4; r++) o[nt][r] = 0.f;

    int qi0 = q0 + rowbase + g;
    int qi1 = qi0 + 8;
    int qe  = q0 + 63;

    for (int seg = 0; seg < 2; seg++) {
        const float* kp = (seg == 0) ? kA : kB;
        const float* vp = (seg == 0) ? vA : vB;
        int lim;
        if (seg == 0)           lim = qe;
        else if (mode == 0)     lim = qe / ntc;
        else                    lim = ntc * (qe + 1) - 1;
        if (lim > T_ - 1) lim = T_ - 1;
        int ntiles = (lim >> 6) + 1;

        const float* kbb = kp + (size_t)b * T_ * OD_ + h * 64;
        const float* vbb = vp + (size_t)b * T_ * OD_ + h * 64;

        for (int t = 0; t < ntiles; t++) {
            int ks = t << 6;
            __syncthreads();
#pragma unroll
            for (int it = 0; it < 8; it++) {
                int idx = tid + it * 128;
                int row = idx >> 4;
                int dq  = (idx & 15) << 2;
                float4 v = *(const float4*)(kbb + (size_t)(ks + row) * OD_ + dq);
                uint4 u;
                u.x = f2tf32(v.x); u.y = f2tf32(v.y);
                u.z = f2tf32(v.z); u.w = f2tf32(v.w);
                *(uint4*)&KPs[row][dq] = u;
                float4 w = *(const float4*)(vbb + (size_t)(ks + row) * OD_ + dq);
                uint4 uw;
                uw.x = f2tf32(w.x); uw.y = f2tf32(w.y);
                uw.z = f2tf32(w.z); uw.w = f2tf32(w.w);
                *(uint4*)&Vs[row][dq] = uw;
            }
            __syncthreads();

            // ---- S = Q K^T ----
            float s[8][4];
#pragma unroll
            for (int nt = 0; nt < 8; nt++)
#pragma unroll
                for (int r = 0; r < 4; r++) s[nt][r] = 0.f;
#pragma unroll
            for (int st = 0; st < 8; st++) {
#pragma unroll
                for (int nt = 0; nt < 8; nt++) {
                    uint32_t bf[2];
                    bf[0] = KPs[nt * 8 + g][st * 8 + tg];
                    bf[1] = KPs[nt * 8 + g][st * 8 + tg + 4];
                    mma_tf32(s[nt], qf[st], bf);
                }
            }
            __syncthreads();

            // ---- Mask + online softmax ----
            float mx0 = -1e30f, mx1 = -1e30f;
#pragma unroll
            for (int nt = 0; nt < 8; nt++) {
                int kj0 = ks + nt * 8 + 2 * tg;
                int kj1 = kj0 + 1;
                bool a00, a01, a10, a11;
                if (seg == 0) {
                    a00 = kj0 <= qi0; a01 = kj1 <= qi0;
                    a10 = kj0 <= qi1; a11 = kj1 <= qi1;
                } else if (mode == 0) {
                    a00 = kj0 * ntc <= qi0; a01 = kj1 * ntc <= qi0;
                    a10 = kj0 * ntc <= qi1; a11 = kj1 * ntc <= qi1;
                } else {
                    a00 = kj0 < ntc * (qi0 + 1); a01 = kj1 < ntc * (qi0 + 1);
                    a10 = kj0 < ntc * (qi1 + 1); a11 = kj1 < ntc * (qi1 + 1);
                }
                s[nt][0] = a00 ? s[nt][0] : -1e30f;
                s[nt][1] = a01 ? s[nt][1] : -1e30f;
                s[nt][2] = a10 ? s[nt][2] : -1e30f;
                s[nt][3] = a11 ? s[nt][3] : -1e30f;
                mx0 = fmaxf(mx0, fmaxf(s[nt][0], s[nt][1]));
                mx1 = fmaxf(mx1, fmaxf(s[nt][2], s[nt][3]));
            }
            mx0 = fmaxf(mx0, __shfl_xor_sync(0xffffffffu, mx0, 1));
            mx0 = fmaxf(mx0, __shfl_xor_sync(0xffffffffu, mx0, 2));
            mx1 = fmaxf(mx1, __shfl_xor_sync(0xffffffffu, mx1, 1));
            mx1 = fmaxf(mx1, __shfl_xor_sync(0xffffffffu, mx1, 2));

            float mn0 = fmaxf(m0r, mx0);
            float mn1 = fmaxf(m1r, mx1);
            float al0 = __expf(m0r - mn0);
            float al1 = __expf(m1r - mn1);
            float sum0 = 0.f, sum1 = 0.f;
            int r0 = rowbase + g;
#pragma unroll
            for (int nt = 0; nt < 8; nt++) {
                float p00 = __expf(s[nt][0] - mn0);
                float p01 = __expf(s[nt][1] - mn0);
                float p10 = __expf(s[nt][2] - mn1);
                float p11 = __expf(s[nt][3] - mn1);
                sum0 += p00 + p01;
                sum1 += p10 + p11;
                int c = nt * 8 + 2 * tg;
                uint2 u0, u1;
                u0.x = f2tf32(p00); u0.y = f2tf32(p01);
                u1.x = f2tf32(p10); u1.y = f2tf32(p11);
                *(uint2*)&KPs[r0][c]     = u0;
                *(uint2*)&KPs[r0 + 8][c] = u1;
            }
            sum0 += __shfl_xor_sync(0xffffffffu, sum0, 1);
            sum0 += __shfl_xor_sync(0xffffffffu, sum0, 2);
            sum1 += __shfl_xor_sync(0xffffffffu, sum1, 1);
            sum1 += __shfl_xor_sync(0xffffffffu, sum1, 2);
            l0 = l0 * al0 + sum0;
            l1 = l1 * al1 + sum1;
            m0r = mn0;
            m1r = mn1;
#pragma unroll
            for (int nt = 0; nt < 8; nt++) {
                o[nt][0] *= al0; o[nt][1] *= al0;
                o[nt][2] *= al1; o[nt][3] *= al1;
            }
            __syncwarp();   // P rows are warp-local

            // ---- O += P V ----
#pragma unroll
            for (int st = 0; st < 8; st++) {
                uint32_t af[4];
                int c = st * 8 + tg;
                af[0] = KPs[rowbase + g][c];
                af[1] = KPs[rowbase + g + 8][c];
                af[2] = KPs[rowbase + g][c + 4];
                af[3] = KPs[rowbase + g + 8][c + 4];
#pragma unroll
                for (int nt = 0; nt < 8; nt++) {
                    uint32_t bf[2];
                    bf[0] = Vs[st * 8 + tg][nt * 8 + g];
                    bf[1] = Vs[st * 8 + tg + 4][nt * 8 + g];
                    mma_tf32(o[nt], af, bf);
                }
            }
        }
    }

    // ---- Epilogue: normalize, store ----
    float inv0 = 1.f / l0;
    float inv1 = 1.f / l1;
    int row0 = q0 + rowbase + g;
    float* ob = Out + (size_t)b * T_ * 1024 + h * 64;
#pragma unroll
    for (int nt = 0; nt < 8; nt++) {
        int col = nt * 8 + 2 * tg;
        float2 v0, v1;
        v0.x = o[nt][0] * inv0; v0.y = o[nt][1] * inv0;
        v1.x = o[nt][2] * inv1; v1.y = o[nt][3] * inv1;
        *(float2*)(ob + (size_t)row0 * 1024 + col)       = v0;
        *(float2*)(ob + (size_t)(row0 + 8) * 1024 + col) = v1;
    }
}

// ---------------------------------------------------------------------------
extern "C" void kernel_launch(void* const* d_in, const int* in_sizes, int n_in,
                              void* d_out, int out_size)
{
    const float* xt  = (const float*)d_in[0];
    const float* xc  = (const float*)d_in[1];
    const float* Wt  = (const float*)d_in[2];
    const float* bt  = (const float*)d_in[3];
    const float* Wc  = (const float*)d_in[4];
    const float* bc  = (const float*)d_in[5];
    const float* Wtp = (const float*)d_in[6];
    const float* btp = (const float*)d_in[7];
    const float* Wcp = (const float*)d_in[8];
    const float* bcp = (const float*)d_in[9];
    const int*   ntc = (const int*)d_in[10];
    float* out = (float*)d_out;

    float *tok, *con, *yt, *yc;
    cudaGetSymbolAddress((void**)&tok, g_tok);
    cudaGetSymbolAddress((void**)&con, g_con);
    cudaGetSymbolAddress((void**)&yt,  g_yt);
    cudaGetSymbolAddress((void**)&yc,  g_yc);

    const int M = B_ * T_;   // 2048

    // 1) Input projections (tf32, pipelined)
    dim3 g1(OD_ / 128, M / 128);
    gemm_tf32<<<g1, 256>>>(xt, Wt, bt, tok, M, OD_, NE_);
    gemm_tf32<<<g1, 256>>>(xc, Wc, bc, con, M, OD_, CD_);

    // 2) Attention — both passes in one launch
    dim3 ga(T_ / 64, NH_, 2 * B_);
    flash_attn_mma<<<ga, 128>>>(xt, xc, tok, con, yt, yc, ntc);

    // 3) Output projections into d_out: [y_t ; y_c]
    dim3 g2(NE_ / 128, M / 128);
    gemm_tf32<<<g2, 256>>>(yt, Wtp, btp, out,                   M, NE_, NE_);
    gemm_tf32<<<g2, 256>>>(yc, Wcp, bcp, out + (size_t)M * NE_, M, CD_, CD_);
}